// round 16
// baseline (speedup 1.0000x reference)
#include <cuda_runtime.h>
#include <cuda_fp16.h>
#include <math.h>
#include <stdint.h>

#define Bc  64
#define Dc  2048
#define Hc  4096
#define NSc 25
#define STR12 (128 * 4096)
#define SZ3   (128 * 6144)
#define PLANE_A 524288            // fp16 elems per A plane (128 x 4096)

#define NET_STRIDE 117440512ULL   // (4096+4096+6144)*4096*2
#define R1OFF 0ULL
#define R2OFF 33554432ULL
#define R3OFF 67108864ULL
#define LOSCALE 4096.0f
#define INVLOSCALE (1.0f / 4096.0f)

__device__ __half g_Wimg[234881024];   // 470MB
__device__ __half g_A1img[2 * PLANE_A];
__device__ __half g_A2img[2 * PLANE_A];
__device__ __half g_A3img[2 * PLANE_A];
__device__ float g_P1[4 * STR12];
__device__ float g_P2[4 * STR12];
__device__ float g_P3[3 * SZ3];
__device__ float g_posF[Bc * Dc];
__device__ float g_momF[Bc * Dc];
__device__ float g_posB[Bc * Dc];
__device__ float g_momB[Bc * Dc];
__device__ float g_sldF[Bc];
__device__ float g_sldB[Bc];
__device__ float g_bias1[2 * NSc * Hc];

// ---------------- helpers ----------------
// PDL primitives
#define GDC_WAIT()   asm volatile("griddepcontrol.wait;" ::: "memory")
#define GDC_LAUNCH() asm volatile("griddepcontrol.launch_dependents;" ::: "memory")

__device__ __forceinline__ uint32_t smem_u32(const void* p) {
    uint32_t a;
    asm("{ .reg .u64 t; cvta.to.shared.u64 t, %1; cvt.u32.u64 %0, t; }" : "=r"(a) : "l"(p));
    return a;
}
#define LDSM4(r, a) \
    asm volatile("ldmatrix.sync.aligned.m8n8.x4.shared.b16 {%0,%1,%2,%3}, [%4];" \
        : "=r"((r)[0]), "=r"((r)[1]), "=r"((r)[2]), "=r"((r)[3]) : "r"(a))

__device__ __forceinline__ void mma_f32(float* c, const uint32_t* a, const uint32_t* b) {
    asm volatile("mma.sync.aligned.m16n8k16.row.col.f32.f16.f16.f32 "
        "{%0,%1,%2,%3},{%4,%5,%6,%7},{%8,%9},{%0,%1,%2,%3};"
        : "+f"(c[0]), "+f"(c[1]), "+f"(c[2]), "+f"(c[3])
        : "r"(a[0]), "r"(a[1]), "r"(a[2]), "r"(a[3]), "r"(b[0]), "r"(b[1]));
}
__device__ __forceinline__ void mma_f16(uint32_t* c, const uint32_t* a, const uint32_t* b) {
    asm volatile("mma.sync.aligned.m16n8k16.row.col.f16.f16.f16.f16 "
        "{%0,%1},{%2,%3,%4,%5},{%6,%7},{%0,%1};"
        : "+r"(c[0]), "+r"(c[1])
        : "r"(a[0]), "r"(a[1]), "r"(a[2]), "r"(a[3]), "r"(b[0]), "r"(b[1]));
}

// fp16 hi/lo split; lo pre-scaled by 2^12 (cross terms accumulate in a
// SEPARATE f16 accumulator, scaled back once at the epilogue).
__device__ __forceinline__ void split8(const float* v, uint4& h4, uint4& l4) {
    uint32_t h[4], l[4];
#pragma unroll
    for (int i = 0; i < 4; i++) {
        __half a = __float2half_rn(v[2*i]), b = __float2half_rn(v[2*i+1]);
        __half ra = __float2half_rn((v[2*i]   - __half2float(a)) * LOSCALE);
        __half rb = __float2half_rn((v[2*i+1] - __half2float(b)) * LOSCALE);
        h[i] = (uint32_t)__half_as_ushort(a)  | ((uint32_t)__half_as_ushort(b)  << 16);
        l[i] = (uint32_t)__half_as_ushort(ra) | ((uint32_t)__half_as_ushort(rb) << 16);
    }
    h4 = make_uint4(h[0], h[1], h[2], h[3]);
    l4 = make_uint4(l[0], l[1], l[2], l[3]);
}
__device__ __forceinline__ void plane_w8(__half* img, int m, int k, const float* v) {
    uint4 h4, l4;
    split8(v, h4, l4);
    *(uint4*)(img + (size_t)m * 4096 + k) = h4;
    *(uint4*)(img + PLANE_A + (size_t)m * 4096 + k) = l4;
}

// ---------------- pre-loop launch #1 ----------------
__global__ __launch_bounds__(256) void init_all_k(
    const float* __restrict__ position, const float* __restrict__ momf,
    const float* __restrict__ momb, const float* __restrict__ b1,
    const float* __restrict__ Wt, const float* __restrict__ ts)
{
    int idx = blockIdx.x * 256 + threadIdx.x;
    if (idx < Bc * Dc) {
        float p = position[idx];
        g_posF[idx] = p; g_posB[idx] = p;
        g_momF[idx] = momf[idx]; g_momB[idx] = momb[idx];
    }
    if (idx < 2 * NSc * Hc) {
        int h = idx % Hc, s = (idx / Hc) % NSc, n = idx / (Hc * NSc);
        g_bias1[idx] = b1[n * Hc + h]
                     + ts[s * 2 + 0] * Wt[(n * 2 + 0) * Hc + h]
                     + ts[s * 2 + 1] * Wt[(n * 2 + 1) * Hc + h];
    }
    if (idx < Bc) { g_sldF[idx] = 0.f; g_sldB[idx] = 0.f; }
    if (blockIdx.x < 128) {
        int r = blockIdx.x, d0 = threadIdx.x * 8;
        const float* src = position + (size_t)(r & 63) * Dc + d0;
        float xa[8], xb[8];
#pragma unroll
        for (int c = 0; c < 8; c++) { float p = src[c]; xa[c] = p; xb[c] = sinf(p); }
        plane_w8(g_A1img, r, d0, xa);
        plane_w8(g_A1img, r, 2048 + d0, xb);
    }
}

// ---------------- weight transposes (3 launches via j0off) ----------------
__global__ __launch_bounds__(256) void tw_all_k(
    const float* __restrict__ W1, const float* __restrict__ W2,
    const float* __restrict__ Wh, const float* __restrict__ Ws,
    const float* __restrict__ Wtr, const float* __restrict__ Wq, int j0off)
{
    __shared__ float sm[64 * 129];
    const int j0 = blockIdx.x + j0off, kb = blockIdx.y, tid = threadIdx.x;
    const int n = blockIdx.z;
    int gtype, j, NSRC, NTOT;
    size_t dstOff;
    const float *S0, *S1 = nullptr, *S2 = nullptr;
    if (j0 < 32) {
        gtype = 1; j = j0; NSRC = 4096; NTOT = 4096; dstOff = R1OFF;
        S0 = W1 + (size_t)n * Dc * Hc; S1 = W2 + (size_t)n * Dc * Hc;
    } else if (j0 < 64) {
        gtype = 2; j = j0 - 32; NSRC = 4096; NTOT = 4096; dstOff = R2OFF;
        S0 = Wh + (size_t)n * Hc * Hc;
    } else {
        gtype = 3; j = j0 - 64; NSRC = 2048; NTOT = 6144; dstOff = R3OFF;
        S0 = Ws + (size_t)n * Hc * Dc; S1 = Wtr + (size_t)n * Hc * Dc;
        S2 = Wq + (size_t)n * Hc * Dc;
    }
    __half* dst = g_Wimg + (size_t)n * NET_STRIDE + dstOff;

    int n0 = (gtype == 3) ? (j & 15) * 128 : j * 128;
#pragma unroll
    for (int p = 0; p < 8; p++) {
        int kk = p * 8 + (tid >> 5), nn = (tid & 31) * 4;
        int kg = kb * 64 + kk;
        const float* sp;
        if (gtype == 1)      sp = (kg < 2048) ? S0 + (size_t)kg * NSRC : S1 + (size_t)(kg - 2048) * NSRC;
        else if (gtype == 2) sp = S0 + (size_t)kg * NSRC;
        else { const float* W = (j < 16) ? S0 : ((j < 32) ? S1 : S2); sp = W + (size_t)kg * NSRC; }
        float4 vv = *(const float4*)(sp + n0 + nn);
        sm[kk * 129 + nn + 0] = vv.x; sm[kk * 129 + nn + 1] = vv.y;
        sm[kk * 129 + nn + 2] = vv.z; sm[kk * 129 + nn + 3] = vv.w;
    }
    __syncthreads();
    size_t planeStride = (size_t)NTOT * 4096;
    int nbase = j * 128;
#pragma unroll
    for (int p = 0; p < 4; p++) {
        int pi = tid + p * 256;
        int rr = pi >> 3, u = pi & 7;
        float v[8];
#pragma unroll
        for (int c = 0; c < 8; c++) v[c] = sm[(u * 8 + c) * 129 + rr];
        uint4 h4, l4;
        split8(v, h4, l4);
        size_t off = (size_t)(nbase + rr) * 4096 + kb * 64 + u * 8;
        *(uint4*)(dst + off) = h4;
        *(uint4*)(dst + planeStride + off) = l4;
    }
}

// ---------------- HMMA GEMM: C[128 x 64] tile, 4m x 2n warps ----------------
// Stage layout (48KB): Ahi 16K | Alo 16K | Bhi 8K | Blo 8K
#define STAGE 49152

__device__ __forceinline__ void ld_chunk(char* sbase, int tid,
    const __half* Ahi, const __half* Alo,
    const __half* Whi, const __half* Wlo, int kb)
{
#pragma unroll
    for (int it = 0; it < 12; it++) {
        int v = it * 256 + tid;
        const __half* src;
        uint32_t dst;
        if (it < 4) {
            int r = v >> 3, c = v & 7;
            src = Ahi + (size_t)r * 4096 + kb + c * 8;
            dst = smem_u32(sbase + r * 128 + ((c ^ (r & 7)) << 4));
        } else if (it < 8) {
            int w = v - 1024; int r = w >> 3, c = w & 7;
            src = Alo + (size_t)r * 4096 + kb + c * 8;
            dst = smem_u32(sbase + 16384 + r * 128 + ((c ^ (r & 7)) << 4));
        } else if (it < 10) {
            int w = v - 2048; int r = w >> 3, c = w & 7;
            src = Whi + (size_t)r * 4096 + kb + c * 8;
            dst = smem_u32(sbase + 32768 + r * 128 + ((c ^ (r & 7)) << 4));
        } else {
            int w = v - 2560; int r = w >> 3, c = w & 7;
            src = Wlo + (size_t)r * 4096 + kb + c * 8;
            dst = smem_u32(sbase + 40960 + r * 128 + ((c ^ (r & 7)) << 4));
        }
        asm volatile("cp.async.cg.shared.global [%0], [%1], 16;" :: "r"(dst), "l"(src));
    }
    asm volatile("cp.async.commit_group;" ::: "memory");
}

__global__ __launch_bounds__(256, 2) void mma_gemm_k(
    const __half* __restrict__ Aimg, const __half* __restrict__ W,
    float* __restrict__ Pout, int NTOT, int NCHB, int EXTRA, int ZOFF)
{
    extern __shared__ __align__(16) char smem[];
    const int tid = threadIdx.x, wid = tid >> 5, lane = tid & 31;
    const int ntile = blockIdx.x;
    const int zz = (int)blockIdx.z + ZOFF;
    const int nch = NCHB + (zz == 0 ? EXTRA : 0);
    const int kc0 = zz * NCHB + (zz > 0 ? EXTRA : 0);
    const int n0 = ntile * 64;
    const int wm = (wid >> 1) * 32;       // 4 m-groups: 0,32,64,96
    const int wn = (wid & 1) * 32;        // 2 n-groups: 0,32

    const __half* Ahi = Aimg;
    const __half* Alo = Aimg + PLANE_A;
    const __half* Whi = W + (size_t)n0 * 4096;
    const __half* Wlo = W + (size_t)NTOT * 4096 + (size_t)n0 * 4096;

    float acc[2][4][4];
    uint32_t accH[2][4][2];
#pragma unroll
    for (int f = 0; f < 2; f++)
#pragma unroll
        for (int g = 0; g < 4; g++) {
#pragma unroll
            for (int q = 0; q < 4; q++) acc[f][g][q] = 0.f;
            accH[f][g][0] = 0u; accH[f][g][1] = 0u;
        }

    GDC_WAIT();   // PDL: prologue above runs during producer drain

    ld_chunk(smem, tid, Ahi, Alo, Whi, Wlo, kc0 * 64);

    const int sub = lane >> 3;
    const int arow = wm + (lane & 7) + ((sub & 1) ? 8 : 0);
    const int brow = wn + (lane & 7) + ((sub >> 1) ? 8 : 0);

    for (int i = 0; i < nch; i++) {
        asm volatile("cp.async.wait_group 0;" ::: "memory");
        __syncthreads();
        if (i + 1 < nch)
            ld_chunk(smem + ((i + 1) & 1) * STAGE, tid, Ahi, Alo, Whi, Wlo,
                     (kc0 + i + 1) * 64);

        char* sb = smem + (i & 1) * STAGE;
        uint32_t sA = smem_u32(sb);
        uint32_t sB = sA + 32768;
#pragma unroll
        for (int ks = 0; ks < 4; ks++) {
            uint32_t ahi[2][4], alo[2][4], bhi[4][2], blo[4][2];
            int akc = ks * 2 + (sub >> 1);
            int bkc = ks * 2 + (sub & 1);
#pragma unroll
            for (int f = 0; f < 2; f++) {
                int row = arow + f * 16;
                uint32_t ad = sA + row * 128 + ((akc ^ (row & 7)) << 4);
                LDSM4(ahi[f], ad);
                LDSM4(alo[f], ad + 16384);
            }
#pragma unroll
            for (int h = 0; h < 2; h++) {
                int row = brow + h * 16;
                uint32_t bd = sB + row * 128 + ((bkc ^ (row & 7)) << 4);
                uint32_t t[4];
                LDSM4(t, bd);
                bhi[h*2][0] = t[0]; bhi[h*2][1] = t[1];
                bhi[h*2+1][0] = t[2]; bhi[h*2+1][1] = t[3];
                LDSM4(t, bd + 8192);
                blo[h*2][0] = t[0]; blo[h*2][1] = t[1];
                blo[h*2+1][0] = t[2]; blo[h*2+1][1] = t[3];
            }
#pragma unroll
            for (int f = 0; f < 2; f++)
#pragma unroll
                for (int g = 0; g < 4; g++) {
                    mma_f32(acc[f][g], ahi[f], bhi[g]);    // hi*hi  (f32 acc)
                    mma_f16(accH[f][g], ahi[f], blo[g]);   // hi*lo' (f16 acc)
                    mma_f16(accH[f][g], alo[f], bhi[g]);   // lo'*hi (f16 acc)
                }
        }
        __syncthreads();
    }

    float* P = Pout + (size_t)zz * 128 * NTOT;
    int mrow = wm + (lane >> 2);
    int ncol0 = n0 + wn + (lane & 3) * 2;
#pragma unroll
    for (int f = 0; f < 2; f++)
#pragma unroll
        for (int g = 0; g < 4; g++) {
            float2 c01 = __half22float2(*(__half2*)&accH[f][g][0]);
            float2 c23 = __half22float2(*(__half2*)&accH[f][g][1]);
            float q0 = acc[f][g][0] + c01.x * INVLOSCALE;
            float q1 = acc[f][g][1] + c01.y * INVLOSCALE;
            float q2 = acc[f][g][2] + c23.x * INVLOSCALE;
            float q3 = acc[f][g][3] + c23.y * INVLOSCALE;
            size_t o0 = (size_t)(mrow + f * 16) * NTOT + ncol0 + g * 8;
            *(float2*)(P + o0) = make_float2(q0, q1);
            *(float2*)(P + o0 + 8 * NTOT) = make_float2(q2, q3);
        }
    GDC_LAUNCH();   // stores above are this CTA's last dependent-visible work
}

// ---------------- activation: sum 4 split-K partials + bias + relu ----------
__global__ __launch_bounds__(256) void act_k(
    const float* __restrict__ P,
    const float* __restrict__ biasF, const float* __restrict__ biasB,
    __half* __restrict__ outImg)
{
    int idx = blockIdx.x * 256 + threadIdx.x;
    int m = idx >> 9, k0 = (idx & 511) * 8;
    const float* row = P + (size_t)m * 4096 + k0;
    GDC_WAIT();
    float v[8];
#pragma unroll
    for (int h = 0; h < 2; h++) {
        float4 a0 = *(const float4*)(row + h * 4);
        float4 a1 = *(const float4*)(row + STR12 + h * 4);
        float4 a2 = *(const float4*)(row + 2 * STR12 + h * 4);
        float4 a3 = *(const float4*)(row + 3 * STR12 + h * 4);
        v[h*4+0] = a0.x + a1.x + a2.x + a3.x;
        v[h*4+1] = a0.y + a1.y + a2.y + a3.y;
        v[h*4+2] = a0.z + a1.z + a2.z + a3.z;
        v[h*4+3] = a0.w + a1.w + a2.w + a3.w;
    }
    const float* bias = (m < 64) ? biasF : biasB;
#pragma unroll
    for (int c = 0; c < 8; c++) v[c] = fmaxf(v[c] + bias[k0 + c], 0.f);
    plane_w8(outImg, m, k0, v);
    GDC_LAUNCH();
}

// ---------------- leapfrog elementwise + next-input planes ----------------
__global__ __launch_bounds__(256) void ep_k(
    int type, const float* __restrict__ eps,
    const float* __restrict__ bs, const float* __restrict__ cs,
    const float* __restrict__ btr, const float* __restrict__ bq,
    const float* __restrict__ cq,
    const float* cmF, int ciF, const float* cmB, int ciB,
    int nextType, const float* nmF, int niF, const float* nmB, int niB,
    int early)
{
    const int r = blockIdx.x;
    const bool fwd = (r < 64);
    const int sr = fwd ? r : r - 64;
    float* pos = fwd ? g_posF : g_posB;
    float* mom = fwd ? g_momF : g_momB;
    const float* cm = fwd ? cmF : cmB;  const int ci = fwd ? ciF : ciB;
    const float* nm = fwd ? nmF : nmB;  const int ni = fwd ? niF : niB;
    const int d0 = threadIdx.x * 8;
    GDC_WAIT();
    const float e = eps[0];

    float xa[8], xb[8], lds = 0.f;
#pragma unroll
    for (int c = 0; c < 8; c++) {
        int d = d0 + c;
        size_t ro = (size_t)r * 6144 + d;
        size_t so = (size_t)sr * Dc + d;
        float s0 = g_P3[ro] + g_P3[SZ3 + ro] + g_P3[2 * SZ3 + ro];
        float t0 = g_P3[ro + 2048] + g_P3[SZ3 + ro + 2048] + g_P3[2 * SZ3 + ro + 2048];
        float q0 = g_P3[ro + 4096] + g_P3[SZ3 + ro + 4096] + g_P3[2 * SZ3 + ro + 4096];
        float Sv = tanhf(s0 + bs[d]) * expf(cs[d]);
        float Tv = t0 + btr[d];
        float Qv = tanhf(q0 + bq[d]) * expf(cq[d]);
        float etr = expf(e * Qv);
        float p = pos[so], v = mom[so];
        if (type == 1) {
            float gg = sinf(p);
            float sc = (fwd ? 0.5f : -0.5f) * e * Sv;
            float es = expf(sc);
            v = fwd ? (v * es - 0.5f * e * (etr * gg - Tv))
                    : (es * (v + 0.5f * e * (etr * gg - Tv)));
            mom[so] = v;
            lds += sc;
        } else {
            float mk = cm[d]; if (ci) mk = 1.f - mk;
            float mi = 1.f - mk;
            float sc = e * Sv;
            float es = expf(sc);
            p = fwd ? (mk * p + mi * (p * es + e * (etr * v + Tv)))
                    : (mk * p + mi * es * (p - e * (etr * v + Tv)));
            pos[so] = p;
            lds += mi * sc;
        }
        if (nextType == 1) { xa[c] = p; xb[c] = sinf(p); }
        else { float k = nm[d]; if (ni) k = 1.f - k; xa[c] = v; xb[c] = k * p; }
    }
    plane_w8(g_A1img, r, d0, xa);
    plane_w8(g_A1img, r, 2048 + d0, xb);

    // Early release: the next GEMM1 needs only the plane/pos/mom stores above.
    // The sld tail below is consumed only by final_k, whose producer ep is
    // launched with early=0 so it releases at completion.
    if (early) GDC_LAUNCH();

    __shared__ float red[256];
    red[threadIdx.x] = lds;
    __syncthreads();
    for (int s2 = 128; s2 > 0; s2 >>= 1) {
        if (threadIdx.x < s2) red[threadIdx.x] += red[threadIdx.x + s2];
        __syncthreads();
    }
    if (threadIdx.x == 0) { (fwd ? g_sldF : g_sldB)[sr] += red[0]; }
}

// ---------------- final assembly ----------------
__global__ __launch_bounds__(256) void final_k(
    const float* __restrict__ position, const float* __restrict__ momf0,
    const float* __restrict__ momb0, const float* __restrict__ u_dir,
    const float* __restrict__ u_accept, float* __restrict__ out)
{
    const int b = blockIdx.x;
    GDC_WAIT();
    float a7[7] = {0,0,0,0,0,0,0};
    for (int d = threadIdx.x; d < Dc; d += 256) {
        size_t o = (size_t)b * Dc + d;
        float x0 = position[o];  a7[0] += 1.f - cosf(x0);
        float a  = momf0[o];     a7[1] += 0.5f * a * a;
        float c  = momb0[o];     a7[2] += 0.5f * c * c;
        float pf = g_posF[o];    a7[3] += 1.f - cosf(pf);
        float mf = g_momF[o];    a7[4] += 0.5f * mf * mf;
        float pb = g_posB[o];    a7[5] += 1.f - cosf(pb);
        float mb = g_momB[o];    a7[6] += 0.5f * mb * mb;
    }
    __shared__ float red[256];
    __shared__ float tot[7];
    for (int q = 0; q < 7; q++) {
        red[threadIdx.x] = a7[q];
        __syncthreads();
        for (int s2 = 128; s2 > 0; s2 >>= 1) {
            if (threadIdx.x < s2) red[threadIdx.x] += red[threadIdx.x + s2];
            __syncthreads();
        }
        if (threadIdx.x == 0) tot[q] = red[0];
        __syncthreads();
    }
    __shared__ float s_fm, s_am;
    if (threadIdx.x == 0) {
        float df  = (tot[0] + tot[1]) - (tot[3] + tot[4]) + g_sldF[b];
        float apf = expf(fminf(df, 0.f)); if (!isfinite(apf)) apf = 0.f;
        float db  = (tot[0] + tot[2]) - (tot[5] + tot[6]) + g_sldB[b];
        float apb = expf(fminf(db, 0.f)); if (!isfinite(apb)) apb = 0.f;
        float fm  = (u_dir[b] > 0.5f) ? 1.f : 0.f;
        float ap  = fm * apf + (1.f - fm) * apb;
        out[2 * Bc * Dc + b] = ap;
        s_fm = fm;
        s_am = (ap > u_accept[b]) ? 1.f : 0.f;
    }
    __syncthreads();
    const float fm = s_fm, am = s_am;
    for (int d = threadIdx.x; d < Dc; d += 256) {
        size_t o = (size_t)b * Dc + d;
        float pp = fm * g_posF[o] + (1.f - fm) * g_posB[o];
        float mp = fm * g_momF[o] + (1.f - fm) * g_momB[o];
        out[o] = pp;
        out[(size_t)Bc * Dc + o] = mp;
        out[(size_t)2 * Bc * Dc + Bc + o] = am * pp + (1.f - am) * position[o];
    }
}

// ---------------- host driver ----------------
static cudaLaunchAttribute g_pdlAttr[1];

static inline cudaLaunchConfig_t pdl_cfg(dim3 g, dim3 b, size_t smem) {
    cudaLaunchConfig_t c = {};
    c.gridDim = g; c.blockDim = b; c.dynamicSmemBytes = smem;
    c.stream = 0;
    c.attrs = g_pdlAttr;
    c.numAttrs = 1;
    return c;
}

extern "C" void kernel_launch(void* const* d_in, const int* in_sizes, int n_in,
                              void* d_out, int out_size)
{
    const float* position = (const float*)d_in[0];
    const float* momf     = (const float*)d_in[1];
    const float* momb     = (const float*)d_in[2];
    const float* u_dir    = (const float*)d_in[3];
    const float* u_acc    = (const float*)d_in[4];
    const float* eps      = (const float*)d_in[5];
    const float* masks    = (const float*)d_in[6];
    const float* ts       = (const float*)d_in[7];
    const float* W1       = (const float*)d_in[8];
    const float* W2       = (const float*)d_in[9];
    const float* Wt       = (const float*)d_in[10];
    const float* b1       = (const float*)d_in[11];
    const float* Wh       = (const float*)d_in[12];
    const float* bh       = (const float*)d_in[13];
    const float* Ws       = (const float*)d_in[14];
    const float* bs       = (const float*)d_in[15];
    const float* cs       = (const float*)d_in[16];
    const float* Wtr      = (const float*)d_in[17];
    const float* btr      = (const float*)d_in[18];
    const float* Wq       = (const float*)d_in[19];
    const float* bq       = (const float*)d_in[20];
    const float* cq       = (const float*)d_in[21];
    float* out = (float*)d_out;

    g_pdlAttr[0].id = cudaLaunchAttributeProgrammaticStreamSerialization;
    g_pdlAttr[0].val.programmaticStreamSerializationAllowed = 1;

    const int DSM = 2 * STAGE;   // 96KB -> 2 CTAs/SM
    cudaFuncSetAttribute(mma_gemm_k, cudaFuncAttributeMaxDynamicSharedMemorySize, DSM);

    void *pW, *pA1, *pA2, *pA3, *pP1, *pP2, *pP3, *pBias;
    cudaGetSymbolAddress(&pW,  g_Wimg);
    cudaGetSymbolAddress(&pA1, g_A1img);
    cudaGetSymbolAddress(&pA2, g_A2img);
    cudaGetSymbolAddress(&pA3, g_A3img);
    cudaGetSymbolAddress(&pP1, g_P1);
    cudaGetSymbolAddress(&pP2, g_P2);
    cudaGetSymbolAddress(&pP3, g_P3);
    cudaGetSymbolAddress(&pBias, g_bias1);
    __half* Wimg = (__half*)pW;
    const float* bias1d = (const float*)pBias;

    // pre-loop: 4 launches (plain)
    init_all_k<<<800, 256>>>(position, momf, momb, b1, Wt, ts);
    tw_all_k<<<dim3(32, 64, 2), 256>>>(W1, W2, Wh, Ws, Wtr, Wq, 0);
    tw_all_k<<<dim3(32, 64, 2), 256>>>(W1, W2, Wh, Ws, Wtr, Wq, 32);
    tw_all_k<<<dim3(48, 64, 2), 256>>>(W1, W2, Wh, Ws, Wtr, Wq, 64);

    for (int step = 0; step < NSc; step++) {
        const int sF = step, sB = NSc - 1 - step;
        const float* mF = masks + (size_t)sF * Dc;
        const float* mB = masks + (size_t)sB * Dc;

        for (int sub = 0; sub < 4; sub++) {
            const int n = (sub == 0 || sub == 3) ? 1 : 0;   // MOM=1, POS=0
            __half* base = Wimg + (size_t)n * NET_STRIDE;

            // GEMM1 reuse (R13/R14): full skip at sub0 step>0; half (ZOFF=2)
            // at sub2 (Xa=mom unchanged since sub1).
            if (sub == 0 && step > 0) {
                // full skip
            } else if (sub == 2) {
                cudaLaunchConfig_t c = pdl_cfg(dim3(64, 1, 2), dim3(256), DSM);
                cudaLaunchKernelEx(&c, mma_gemm_k,
                    (const __half*)pA1, (const __half*)(base + R1OFF),
                    (float*)pP1, 4096, 16, 0, 2);
            } else {
                cudaLaunchConfig_t c = pdl_cfg(dim3(64, 1, 4), dim3(256), DSM);
                cudaLaunchKernelEx(&c, mma_gemm_k,
                    (const __half*)pA1, (const __half*)(base + R1OFF),
                    (float*)pP1, 4096, 16, 0, 0);
            }
            {
                cudaLaunchConfig_t c = pdl_cfg(dim3(256), dim3(256), 0);
                cudaLaunchKernelEx(&c, act_k, (const float*)pP1,
                    (const float*)(bias1d + ((size_t)n * NSc + sF) * Hc),
                    (const float*)(bias1d + ((size_t)n * NSc + sB) * Hc),
                    (__half*)pA2);
            }
            {
                cudaLaunchConfig_t c = pdl_cfg(dim3(64, 1, 4), dim3(256), DSM);
                cudaLaunchKernelEx(&c, mma_gemm_k,
                    (const __half*)pA2, (const __half*)(base + R2OFF),
                    (float*)pP2, 4096, 16, 0, 0);
            }
            {
                cudaLaunchConfig_t c = pdl_cfg(dim3(256), dim3(256), 0);
                cudaLaunchKernelEx(&c, act_k, (const float*)pP2,
                    (const float*)(bh + (size_t)n * Hc),
                    (const float*)(bh + (size_t)n * Hc),
                    (__half*)pA3);
            }
            {
                cudaLaunchConfig_t c = pdl_cfg(dim3(96, 1, 3), dim3(256), DSM);
                cudaLaunchKernelEx(&c, mma_gemm_k,
                    (const __half*)pA3, (const __half*)(base + R3OFF),
                    (float*)pP3, 6144, 21, 1, 0);
            }

            int type, nextType;
            const float *cmF = nullptr, *cmB = nullptr, *nmF = nullptr, *nmB = nullptr;
            int ciF = 0, ciB = 0, niF = 0, niB = 0;
            if (sub == 0) {
                type = 1; nextType = 0; nmF = mF; niF = 0; nmB = mB; niB = 1;
            } else if (sub == 1) {
                type = 0; nextType = 0;
                cmF = mF; ciF = 0; cmB = mB; ciB = 1;
                nmF = mF; niF = 1; nmB = mB; niB = 0;
            } else if (sub == 2) {
                type = 0; nextType = 1; cmF = mF; ciF = 1; cmB = mB; ciB = 0;
            } else {
                type = 1; nextType = 1;
            }
            {
                // last ep (step 24, sub 3) must release at completion so
                // final_k sees the g_sld accumulation.
                const int early = !(step == NSc - 1 && sub == 3);
                cudaLaunchConfig_t c = pdl_cfg(dim3(128), dim3(256), 0);
                cudaLaunchKernelEx(&c, ep_k, type, eps,
                    (const float*)(bs + (size_t)n * Dc),
                    (const float*)(cs + (size_t)n * Dc),
                    (const float*)(btr + (size_t)n * Dc),
                    (const float*)(bq + (size_t)n * Dc),
                    (const float*)(cq + (size_t)n * Dc),
                    cmF, ciF, cmB, ciB,
                    nextType, nmF, niF, nmB, niB, early);
            }
        }
    }

    {
        cudaLaunchConfig_t c = pdl_cfg(dim3(64), dim3(256), 0);
        cudaLaunchKernelEx(&c, final_k, position, momf, momb, u_dir, u_acc, out);
    }
}

// round 17
// speedup vs baseline: 1.0115x; 1.0115x over previous
#include <cuda_runtime.h>
#include <cuda_fp16.h>
#include <math.h>
#include <stdint.h>

#define Bc  64
#define Dc  2048
#define Hc  4096
#define NSc 25
#define STR12 (128 * 4096)
#define SZ3   (128 * 6144)
#define PLANE_A 524288            // fp16 elems per A plane (128 x 4096)

#define NET_STRIDE 117440512ULL   // (4096+4096+6144)*4096*2
#define R1OFF 0ULL
#define R2OFF 33554432ULL
#define R3OFF 67108864ULL
#define LOSCALE 4096.0f
#define INVLOSCALE (1.0f / 4096.0f)

__device__ __half g_Wimg[234881024];   // 470MB
__device__ __half g_A1img[2 * PLANE_A];
__device__ __half g_A2img[2 * PLANE_A];
__device__ __half g_A3img[2 * PLANE_A];
__device__ float g_P1[6 * STR12];      // up to 6 split-K planes (sub2 path)
__device__ float g_P2[4 * STR12];
__device__ float g_P3[3 * SZ3];
__device__ float g_posF[Bc * Dc];
__device__ float g_momF[Bc * Dc];
__device__ float g_posB[Bc * Dc];
__device__ float g_momB[Bc * Dc];
__device__ float g_sldF[Bc];
__device__ float g_sldB[Bc];
__device__ float g_bias1[2 * NSc * Hc];

// ---------------- helpers ----------------
#define GDC_WAIT() asm volatile("griddepcontrol.wait;" ::: "memory")

__device__ __forceinline__ uint32_t smem_u32(const void* p) {
    uint32_t a;
    asm("{ .reg .u64 t; cvta.to.shared.u64 t, %1; cvt.u32.u64 %0, t; }" : "=r"(a) : "l"(p));
    return a;
}
#define LDSM4(r, a) \
    asm volatile("ldmatrix.sync.aligned.m8n8.x4.shared.b16 {%0,%1,%2,%3}, [%4];" \
        : "=r"((r)[0]), "=r"((r)[1]), "=r"((r)[2]), "=r"((r)[3]) : "r"(a))

__device__ __forceinline__ void mma_f32(float* c, const uint32_t* a, const uint32_t* b) {
    asm volatile("mma.sync.aligned.m16n8k16.row.col.f32.f16.f16.f32 "
        "{%0,%1,%2,%3},{%4,%5,%6,%7},{%8,%9},{%0,%1,%2,%3};"
        : "+f"(c[0]), "+f"(c[1]), "+f"(c[2]), "+f"(c[3])
        : "r"(a[0]), "r"(a[1]), "r"(a[2]), "r"(a[3]), "r"(b[0]), "r"(b[1]));
}
__device__ __forceinline__ void mma_f16(uint32_t* c, const uint32_t* a, const uint32_t* b) {
    asm volatile("mma.sync.aligned.m16n8k16.row.col.f16.f16.f16.f16 "
        "{%0,%1},{%2,%3,%4,%5},{%6,%7},{%0,%1};"
        : "+r"(c[0]), "+r"(c[1])
        : "r"(a[0]), "r"(a[1]), "r"(a[2]), "r"(a[3]), "r"(b[0]), "r"(b[1]));
}

// fp16 hi/lo split; lo pre-scaled by 2^12 (cross terms accumulate in a
// SEPARATE f16 accumulator, scaled back once at the epilogue).
__device__ __forceinline__ void split8(const float* v, uint4& h4, uint4& l4) {
    uint32_t h[4], l[4];
#pragma unroll
    for (int i = 0; i < 4; i++) {
        __half a = __float2half_rn(v[2*i]), b = __float2half_rn(v[2*i+1]);
        __half ra = __float2half_rn((v[2*i]   - __half2float(a)) * LOSCALE);
        __half rb = __float2half_rn((v[2*i+1] - __half2float(b)) * LOSCALE);
        h[i] = (uint32_t)__half_as_ushort(a)  | ((uint32_t)__half_as_ushort(b)  << 16);
        l[i] = (uint32_t)__half_as_ushort(ra) | ((uint32_t)__half_as_ushort(rb) << 16);
    }
    h4 = make_uint4(h[0], h[1], h[2], h[3]);
    l4 = make_uint4(l[0], l[1], l[2], l[3]);
}
__device__ __forceinline__ void plane_w8(__half* img, int m, int k, const float* v) {
    uint4 h4, l4;
    split8(v, h4, l4);
    *(uint4*)(img + (size_t)m * 4096 + k) = h4;
    *(uint4*)(img + PLANE_A + (size_t)m * 4096 + k) = l4;
}

// ---------------- pre-loop launch #1 ----------------
__global__ __launch_bounds__(256) void init_all_k(
    const float* __restrict__ position, const float* __restrict__ momf,
    const float* __restrict__ momb, const float* __restrict__ b1,
    const float* __restrict__ Wt, const float* __restrict__ ts)
{
    int idx = blockIdx.x * 256 + threadIdx.x;
    if (idx < Bc * Dc) {
        float p = position[idx];
        g_posF[idx] = p; g_posB[idx] = p;
        g_momF[idx] = momf[idx]; g_momB[idx] = momb[idx];
    }
    if (idx < 2 * NSc * Hc) {
        int h = idx % Hc, s = (idx / Hc) % NSc, n = idx / (Hc * NSc);
        g_bias1[idx] = b1[n * Hc + h]
                     + ts[s * 2 + 0] * Wt[(n * 2 + 0) * Hc + h]
                     + ts[s * 2 + 1] * Wt[(n * 2 + 1) * Hc + h];
    }
    if (idx < Bc) { g_sldF[idx] = 0.f; g_sldB[idx] = 0.f; }
    if (blockIdx.x < 128) {
        int r = blockIdx.x, d0 = threadIdx.x * 8;
        const float* src = position + (size_t)(r & 63) * Dc + d0;
        float xa[8], xb[8];
#pragma unroll
        for (int c = 0; c < 8; c++) { float p = src[c]; xa[c] = p; xb[c] = sinf(p); }
        plane_w8(g_A1img, r, d0, xa);
        plane_w8(g_A1img, r, 2048 + d0, xb);
    }
}

// ---------------- weight transposes (3 launches via j0off) ----------------
__global__ __launch_bounds__(256) void tw_all_k(
    const float* __restrict__ W1, const float* __restrict__ W2,
    const float* __restrict__ Wh, const float* __restrict__ Ws,
    const float* __restrict__ Wtr, const float* __restrict__ Wq, int j0off)
{
    __shared__ float sm[64 * 129];
    const int j0 = blockIdx.x + j0off, kb = blockIdx.y, tid = threadIdx.x;
    const int n = blockIdx.z;
    int gtype, j, NSRC, NTOT;
    size_t dstOff;
    const float *S0, *S1 = nullptr, *S2 = nullptr;
    if (j0 < 32) {
        gtype = 1; j = j0; NSRC = 4096; NTOT = 4096; dstOff = R1OFF;
        S0 = W1 + (size_t)n * Dc * Hc; S1 = W2 + (size_t)n * Dc * Hc;
    } else if (j0 < 64) {
        gtype = 2; j = j0 - 32; NSRC = 4096; NTOT = 4096; dstOff = R2OFF;
        S0 = Wh + (size_t)n * Hc * Hc;
    } else {
        gtype = 3; j = j0 - 64; NSRC = 2048; NTOT = 6144; dstOff = R3OFF;
        S0 = Ws + (size_t)n * Hc * Dc; S1 = Wtr + (size_t)n * Hc * Dc;
        S2 = Wq + (size_t)n * Hc * Dc;
    }
    __half* dst = g_Wimg + (size_t)n * NET_STRIDE + dstOff;

    int n0 = (gtype == 3) ? (j & 15) * 128 : j * 128;
#pragma unroll
    for (int p = 0; p < 8; p++) {
        int kk = p * 8 + (tid >> 5), nn = (tid & 31) * 4;
        int kg = kb * 64 + kk;
        const float* sp;
        if (gtype == 1)      sp = (kg < 2048) ? S0 + (size_t)kg * NSRC : S1 + (size_t)(kg - 2048) * NSRC;
        else if (gtype == 2) sp = S0 + (size_t)kg * NSRC;
        else { const float* W = (j < 16) ? S0 : ((j < 32) ? S1 : S2); sp = W + (size_t)kg * NSRC; }
        float4 vv = *(const float4*)(sp + n0 + nn);
        sm[kk * 129 + nn + 0] = vv.x; sm[kk * 129 + nn + 1] = vv.y;
        sm[kk * 129 + nn + 2] = vv.z; sm[kk * 129 + nn + 3] = vv.w;
    }
    __syncthreads();
    size_t planeStride = (size_t)NTOT * 4096;
    int nbase = j * 128;
#pragma unroll
    for (int p = 0; p < 4; p++) {
        int pi = tid + p * 256;
        int rr = pi >> 3, u = pi & 7;
        float v[8];
#pragma unroll
        for (int c = 0; c < 8; c++) v[c] = sm[(u * 8 + c) * 129 + rr];
        uint4 h4, l4;
        split8(v, h4, l4);
        size_t off = (size_t)(nbase + rr) * 4096 + kb * 64 + u * 8;
        *(uint4*)(dst + off) = h4;
        *(uint4*)(dst + planeStride + off) = l4;
    }
}

// ---------------- HMMA GEMM: C[128 x 64] tile, 4m x 2n warps ----------------
// Stage layout (48KB): Ahi 16K | Alo 16K | Bhi 8K | Blo 8K
// PBASE: output plane offset; KB0: K-chunk base (plane = z+PBASE,
// kc0 = KB0 + z*NCHB + extra-carry). Used for the sub2 partial recompute.
#define STAGE 49152

__device__ __forceinline__ void ld_chunk(char* sbase, int tid,
    const __half* Ahi, const __half* Alo,
    const __half* Whi, const __half* Wlo, int kb)
{
#pragma unroll
    for (int it = 0; it < 12; it++) {
        int v = it * 256 + tid;
        const __half* src;
        uint32_t dst;
        if (it < 4) {
            int r = v >> 3, c = v & 7;
            src = Ahi + (size_t)r * 4096 + kb + c * 8;
            dst = smem_u32(sbase + r * 128 + ((c ^ (r & 7)) << 4));
        } else if (it < 8) {
            int w = v - 1024; int r = w >> 3, c = w & 7;
            src = Alo + (size_t)r * 4096 + kb + c * 8;
            dst = smem_u32(sbase + 16384 + r * 128 + ((c ^ (r & 7)) << 4));
        } else if (it < 10) {
            int w = v - 2048; int r = w >> 3, c = w & 7;
            src = Whi + (size_t)r * 4096 + kb + c * 8;
            dst = smem_u32(sbase + 32768 + r * 128 + ((c ^ (r & 7)) << 4));
        } else {
            int w = v - 2560; int r = w >> 3, c = w & 7;
            src = Wlo + (size_t)r * 4096 + kb + c * 8;
            dst = smem_u32(sbase + 40960 + r * 128 + ((c ^ (r & 7)) << 4));
        }
        asm volatile("cp.async.cg.shared.global [%0], [%1], 16;" :: "r"(dst), "l"(src));
    }
    asm volatile("cp.async.commit_group;" ::: "memory");
}

__global__ __launch_bounds__(256, 2) void mma_gemm_k(
    const __half* __restrict__ Aimg, const __half* __restrict__ W,
    float* __restrict__ Pout, int NTOT, int NCHB, int EXTRA,
    int PBASE, int KB0)
{
    extern __shared__ __align__(16) char smem[];
    const int tid = threadIdx.x, wid = tid >> 5, lane = tid & 31;
    const int ntile = blockIdx.x;
    const int z = (int)blockIdx.z;
    const int zz = z + PBASE;                         // output plane
    const int nch = NCHB + (z == 0 ? EXTRA : 0);
    const int kc0 = KB0 + z * NCHB + (z > 0 ? EXTRA : 0);
    const int n0 = ntile * 64;
    const int wm = (wid >> 1) * 32;       // 4 m-groups: 0,32,64,96
    const int wn = (wid & 1) * 32;        // 2 n-groups: 0,32

    const __half* Ahi = Aimg;
    const __half* Alo = Aimg + PLANE_A;
    const __half* Whi = W + (size_t)n0 * 4096;
    const __half* Wlo = W + (size_t)NTOT * 4096 + (size_t)n0 * 4096;

    float acc[2][4][4];
    uint32_t accH[2][4][2];
#pragma unroll
    for (int f = 0; f < 2; f++)
#pragma unroll
        for (int g = 0; g < 4; g++) {
#pragma unroll
            for (int q = 0; q < 4; q++) acc[f][g][q] = 0.f;
            accH[f][g][0] = 0u; accH[f][g][1] = 0u;
        }

    GDC_WAIT();   // PDL: prologue above runs during producer drain

    ld_chunk(smem, tid, Ahi, Alo, Whi, Wlo, kc0 * 64);

    const int sub = lane >> 3;
    const int arow = wm + (lane & 7) + ((sub & 1) ? 8 : 0);
    const int brow = wn + (lane & 7) + ((sub >> 1) ? 8 : 0);

    for (int i = 0; i < nch; i++) {
        asm volatile("cp.async.wait_group 0;" ::: "memory");
        __syncthreads();
        if (i + 1 < nch)
            ld_chunk(smem + ((i + 1) & 1) * STAGE, tid, Ahi, Alo, Whi, Wlo,
                     (kc0 + i + 1) * 64);

        char* sb = smem + (i & 1) * STAGE;
        uint32_t sA = smem_u32(sb);
        uint32_t sB = sA + 32768;
#pragma unroll
        for (int ks = 0; ks < 4; ks++) {
            uint32_t ahi[2][4], alo[2][4], bhi[4][2], blo[4][2];
            int akc = ks * 2 + (sub >> 1);
            int bkc = ks * 2 + (sub & 1);
#pragma unroll
            for (int f = 0; f < 2; f++) {
                int row = arow + f * 16;
                uint32_t ad = sA + row * 128 + ((akc ^ (row & 7)) << 4);
                LDSM4(ahi[f], ad);
                LDSM4(alo[f], ad + 16384);
            }
#pragma unroll
            for (int h = 0; h < 2; h++) {
                int row = brow + h * 16;
                uint32_t bd = sB + row * 128 + ((bkc ^ (row & 7)) << 4);
                uint32_t t[4];
                LDSM4(t, bd);
                bhi[h*2][0] = t[0]; bhi[h*2][1] = t[1];
                bhi[h*2+1][0] = t[2]; bhi[h*2+1][1] = t[3];
                LDSM4(t, bd + 8192);
                blo[h*2][0] = t[0]; blo[h*2][1] = t[1];
                blo[h*2+1][0] = t[2]; blo[h*2+1][1] = t[3];
            }
#pragma unroll
            for (int f = 0; f < 2; f++)
#pragma unroll
                for (int g = 0; g < 4; g++) {
                    mma_f32(acc[f][g], ahi[f], bhi[g]);    // hi*hi  (f32 acc)
                    mma_f16(accH[f][g], ahi[f], blo[g]);   // hi*lo' (f16 acc)
                    mma_f16(accH[f][g], alo[f], bhi[g]);   // lo'*hi (f16 acc)
                }
        }
        __syncthreads();
    }

    float* P = Pout + (size_t)zz * 128 * NTOT;
    int mrow = wm + (lane >> 2);
    int ncol0 = n0 + wn + (lane & 3) * 2;
#pragma unroll
    for (int f = 0; f < 2; f++)
#pragma unroll
        for (int g = 0; g < 4; g++) {
            float2 c01 = __half22float2(*(__half2*)&accH[f][g][0]);
            float2 c23 = __half22float2(*(__half2*)&accH[f][g][1]);
            float q0 = acc[f][g][0] + c01.x * INVLOSCALE;
            float q1 = acc[f][g][1] + c01.y * INVLOSCALE;
            float q2 = acc[f][g][2] + c23.x * INVLOSCALE;
            float q3 = acc[f][g][3] + c23.y * INVLOSCALE;
            size_t o0 = (size_t)(mrow + f * 16) * NTOT + ncol0 + g * 8;
            *(float2*)(P + o0) = make_float2(q0, q1);
            *(float2*)(P + o0 + 8 * NTOT) = make_float2(q2, q3);
        }
}

// ---------------- activation: sum NP split-K partials + bias + relu ---------
__global__ __launch_bounds__(256) void act_k(
    const float* __restrict__ P, int NP,
    const float* __restrict__ biasF, const float* __restrict__ biasB,
    __half* __restrict__ outImg)
{
    int idx = blockIdx.x * 256 + threadIdx.x;
    int m = idx >> 9, k0 = (idx & 511) * 8;
    const float* row = P + (size_t)m * 4096 + k0;
    GDC_WAIT();
    float v[8];
#pragma unroll
    for (int h = 0; h < 2; h++) {
        float4 a0 = *(const float4*)(row + h * 4);
        float4 a1 = *(const float4*)(row + STR12 + h * 4);
        float4 a2 = *(const float4*)(row + 2 * STR12 + h * 4);
        float4 a3 = *(const float4*)(row + 3 * STR12 + h * 4);
        v[h*4+0] = a0.x + a1.x + a2.x + a3.x;
        v[h*4+1] = a0.y + a1.y + a2.y + a3.y;
        v[h*4+2] = a0.z + a1.z + a2.z + a3.z;
        v[h*4+3] = a0.w + a1.w + a2.w + a3.w;
    }
    if (NP == 6) {
#pragma unroll
        for (int h = 0; h < 2; h++) {
            float4 a4 = *(const float4*)(row + 4 * STR12 + h * 4);
            float4 a5 = *(const float4*)(row + 5 * STR12 + h * 4);
            v[h*4+0] += a4.x + a5.x;
            v[h*4+1] += a4.y + a5.y;
            v[h*4+2] += a4.z + a5.z;
            v[h*4+3] += a4.w + a5.w;
        }
    }
    const float* bias = (m < 64) ? biasF : biasB;
#pragma unroll
    for (int c = 0; c < 8; c++) v[c] = fmaxf(v[c] + bias[k0 + c], 0.f);
    plane_w8(outImg, m, k0, v);
}

// ---------------- leapfrog elementwise + next-input planes ----------------
__global__ __launch_bounds__(256) void ep_k(
    int type, const float* __restrict__ eps,
    const float* __restrict__ bs, const float* __restrict__ cs,
    const float* __restrict__ btr, const float* __restrict__ bq,
    const float* __restrict__ cq,
    const float* cmF, int ciF, const float* cmB, int ciB,
    int nextType, const float* nmF, int niF, const float* nmB, int niB)
{
    const int r = blockIdx.x;
    const bool fwd = (r < 64);
    const int sr = fwd ? r : r - 64;
    float* pos = fwd ? g_posF : g_posB;
    float* mom = fwd ? g_momF : g_momB;
    const float* cm = fwd ? cmF : cmB;  const int ci = fwd ? ciF : ciB;
    const float* nm = fwd ? nmF : nmB;  const int ni = fwd ? niF : niB;
    const int d0 = threadIdx.x * 8;
    GDC_WAIT();
    const float e = eps[0];

    float xa[8], xb[8], lds = 0.f;
#pragma unroll
    for (int c = 0; c < 8; c++) {
        int d = d0 + c;
        size_t ro = (size_t)r * 6144 + d;
        size_t so = (size_t)sr * Dc + d;
        float s0 = g_P3[ro] + g_P3[SZ3 + ro] + g_P3[2 * SZ3 + ro];
        float t0 = g_P3[ro + 2048] + g_P3[SZ3 + ro + 2048] + g_P3[2 * SZ3 + ro + 2048];
        float q0 = g_P3[ro + 4096] + g_P3[SZ3 + ro + 4096] + g_P3[2 * SZ3 + ro + 4096];
        float Sv = tanhf(s0 + bs[d]) * expf(cs[d]);
        float Tv = t0 + btr[d];
        float Qv = tanhf(q0 + bq[d]) * expf(cq[d]);
        float etr = expf(e * Qv);
        float p = pos[so], v = mom[so];
        if (type == 1) {
            float gg = sinf(p);
            float sc = (fwd ? 0.5f : -0.5f) * e * Sv;
            float es = expf(sc);
            v = fwd ? (v * es - 0.5f * e * (etr * gg - Tv))
                    : (es * (v + 0.5f * e * (etr * gg - Tv)));
            mom[so] = v;
            lds += sc;
        } else {
            float mk = cm[d]; if (ci) mk = 1.f - mk;
            float mi = 1.f - mk;
            float sc = e * Sv;
            float es = expf(sc);
            p = fwd ? (mk * p + mi * (p * es + e * (etr * v + Tv)))
                    : (mk * p + mi * es * (p - e * (etr * v + Tv)));
            pos[so] = p;
            lds += mi * sc;
        }
        if (nextType == 1) { xa[c] = p; xb[c] = sinf(p); }
        else { float k = nm[d]; if (ni) k = 1.f - k; xa[c] = v; xb[c] = k * p; }
    }
    plane_w8(g_A1img, r, d0, xa);
    plane_w8(g_A1img, r, 2048 + d0, xb);

    __shared__ float red[256];
    red[threadIdx.x] = lds;
    __syncthreads();
    for (int s2 = 128; s2 > 0; s2 >>= 1) {
        if (threadIdx.x < s2) red[threadIdx.x] += red[threadIdx.x + s2];
        __syncthreads();
    }
    if (threadIdx.x == 0) { (fwd ? g_sldF : g_sldB)[sr] += red[0]; }
}

// ---------------- final assembly ----------------
__global__ __launch_bounds__(256) void final_k(
    const float* __restrict__ position, const float* __restrict__ momf0,
    const float* __restrict__ momb0, const float* __restrict__ u_dir,
    const float* __restrict__ u_accept, float* __restrict__ out)
{
    const int b = blockIdx.x;
    GDC_WAIT();
    float a7[7] = {0,0,0,0,0,0,0};
    for (int d = threadIdx.x; d < Dc; d += 256) {
        size_t o = (size_t)b * Dc + d;
        float x0 = position[o];  a7[0] += 1.f - cosf(x0);
        float a  = momf0[o];     a7[1] += 0.5f * a * a;
        float c  = momb0[o];     a7[2] += 0.5f * c * c;
        float pf = g_posF[o];    a7[3] += 1.f - cosf(pf);
        float mf = g_momF[o];    a7[4] += 0.5f * mf * mf;
        float pb = g_posB[o];    a7[5] += 1.f - cosf(pb);
        float mb = g_momB[o];    a7[6] += 0.5f * mb * mb;
    }
    __shared__ float red[256];
    __shared__ float tot[7];
    for (int q = 0; q < 7; q++) {
        red[threadIdx.x] = a7[q];
        __syncthreads();
        for (int s2 = 128; s2 > 0; s2 >>= 1) {
            if (threadIdx.x < s2) red[threadIdx.x] += red[threadIdx.x + s2];
            __syncthreads();
        }
        if (threadIdx.x == 0) tot[q] = red[0];
        __syncthreads();
    }
    __shared__ float s_fm, s_am;
    if (threadIdx.x == 0) {
        float df  = (tot[0] + tot[1]) - (tot[3] + tot[4]) + g_sldF[b];
        float apf = expf(fminf(df, 0.f)); if (!isfinite(apf)) apf = 0.f;
        float db  = (tot[0] + tot[2]) - (tot[5] + tot[6]) + g_sldB[b];
        float apb = expf(fminf(db, 0.f)); if (!isfinite(apb)) apb = 0.f;
        float fm  = (u_dir[b] > 0.5f) ? 1.f : 0.f;
        float ap  = fm * apf + (1.f - fm) * apb;
        out[2 * Bc * Dc + b] = ap;
        s_fm = fm;
        s_am = (ap > u_accept[b]) ? 1.f : 0.f;
    }
    __syncthreads();
    const float fm = s_fm, am = s_am;
    for (int d = threadIdx.x; d < Dc; d += 256) {
        size_t o = (size_t)b * Dc + d;
        float pp = fm * g_posF[o] + (1.f - fm) * g_posB[o];
        float mp = fm * g_momF[o] + (1.f - fm) * g_momB[o];
        out[o] = pp;
        out[(size_t)Bc * Dc + o] = mp;
        out[(size_t)2 * Bc * Dc + Bc + o] = am * pp + (1.f - am) * position[o];
    }
}

// ---------------- host driver ----------------
static cudaLaunchAttribute g_pdlAttr[1];

static inline cudaLaunchConfig_t pdl_cfg(dim3 g, dim3 b, size_t smem) {
    cudaLaunchConfig_t c = {};
    c.gridDim = g; c.blockDim = b; c.dynamicSmemBytes = smem;
    c.stream = 0;
    c.attrs = g_pdlAttr;
    c.numAttrs = 1;
    return c;
}

extern "C" void kernel_launch(void* const* d_in, const int* in_sizes, int n_in,
                              void* d_out, int out_size)
{
    const float* position = (const float*)d_in[0];
    const float* momf     = (const float*)d_in[1];
    const float* momb     = (const float*)d_in[2];
    const float* u_dir    = (const float*)d_in[3];
    const float* u_acc    = (const float*)d_in[4];
    const float* eps      = (const float*)d_in[5];
    const float* masks    = (const float*)d_in[6];
    const float* ts       = (const float*)d_in[7];
    const float* W1       = (const float*)d_in[8];
    const float* W2       = (const float*)d_in[9];
    const float* Wt       = (const float*)d_in[10];
    const float* b1       = (const float*)d_in[11];
    const float* Wh       = (const float*)d_in[12];
    const float* bh       = (const float*)d_in[13];
    const float* Ws       = (const float*)d_in[14];
    const float* bs       = (const float*)d_in[15];
    const float* cs       = (const float*)d_in[16];
    const float* Wtr      = (const float*)d_in[17];
    const float* btr      = (const float*)d_in[18];
    const float* Wq       = (const float*)d_in[19];
    const float* bq       = (const float*)d_in[20];
    const float* cq       = (const float*)d_in[21];
    float* out = (float*)d_out;

    g_pdlAttr[0].id = cudaLaunchAttributeProgrammaticStreamSerialization;
    g_pdlAttr[0].val.programmaticStreamSerializationAllowed = 1;

    const int DSM = 2 * STAGE;   // 96KB -> 2 CTAs/SM
    cudaFuncSetAttribute(mma_gemm_k, cudaFuncAttributeMaxDynamicSharedMemorySize, DSM);

    void *pW, *pA1, *pA2, *pA3, *pP1, *pP2, *pP3, *pBias;
    cudaGetSymbolAddress(&pW,  g_Wimg);
    cudaGetSymbolAddress(&pA1, g_A1img);
    cudaGetSymbolAddress(&pA2, g_A2img);
    cudaGetSymbolAddress(&pA3, g_A3img);
    cudaGetSymbolAddress(&pP1, g_P1);
    cudaGetSymbolAddress(&pP2, g_P2);
    cudaGetSymbolAddress(&pP3, g_P3);
    cudaGetSymbolAddress(&pBias, g_bias1);
    __half* Wimg = (__half*)pW;
    const float* bias1d = (const float*)pBias;

    // pre-loop: 4 launches (plain)
    init_all_k<<<800, 256>>>(position, momf, momb, b1, Wt, ts);
    tw_all_k<<<dim3(32, 64, 2), 256>>>(W1, W2, Wh, Ws, Wtr, Wq, 0);
    tw_all_k<<<dim3(32, 64, 2), 256>>>(W1, W2, Wh, Ws, Wtr, Wq, 32);
    tw_all_k<<<dim3(48, 64, 2), 256>>>(W1, W2, Wh, Ws, Wtr, Wq, 64);

    for (int step = 0; step < NSc; step++) {
        const int sF = step, sB = NSc - 1 - step;
        const float* mF = masks + (size_t)sF * Dc;
        const float* mB = masks + (size_t)sB * Dc;

        for (int sub = 0; sub < 4; sub++) {
            const int n = (sub == 0 || sub == 3) ? 1 : 0;   // MOM=1, POS=0
            __half* base = Wimg + (size_t)n * NET_STRIDE;
            int actNP = 4;

            // GEMM1 reuse:
            //  - sub0, step>0: full skip (pos unchanged since prev sub3).
            //  - sub2: Xa=mom unchanged since sub1 -> planes 0,1 reused;
            //    recompute K 2048-4095 as FOUR 8-chunk slices into planes
            //    2..5 (256 CTAs = full wave) instead of two 16-chunk slices.
            if (sub == 0 && step > 0) {
                // full skip
            } else if (sub == 2) {
                cudaLaunchConfig_t c = pdl_cfg(dim3(64, 1, 4), dim3(256), DSM);
                cudaLaunchKernelEx(&c, mma_gemm_k,
                    (const __half*)pA1, (const __half*)(base + R1OFF),
                    (float*)pP1, 4096, 8, 0, 2, 32);
                actNP = 6;
            } else {
                cudaLaunchConfig_t c = pdl_cfg(dim3(64, 1, 4), dim3(256), DSM);
                cudaLaunchKernelEx(&c, mma_gemm_k,
                    (const __half*)pA1, (const __half*)(base + R1OFF),
                    (float*)pP1, 4096, 16, 0, 0, 0);
            }
            {
                cudaLaunchConfig_t c = pdl_cfg(dim3(256), dim3(256), 0);
                cudaLaunchKernelEx(&c, act_k, (const float*)pP1, actNP,
                    (const float*)(bias1d + ((size_t)n * NSc + sF) * Hc),
                    (const float*)(bias1d + ((size_t)n * NSc + sB) * Hc),
                    (__half*)pA2);
            }
            {
                cudaLaunchConfig_t c = pdl_cfg(dim3(64, 1, 4), dim3(256), DSM);
                cudaLaunchKernelEx(&c, mma_gemm_k,
                    (const __half*)pA2, (const __half*)(base + R2OFF),
                    (float*)pP2, 4096, 16, 0, 0, 0);
            }
            {
                cudaLaunchConfig_t c = pdl_cfg(dim3(256), dim3(256), 0);
                cudaLaunchKernelEx(&c, act_k, (const float*)pP2, 4,
                    (const float*)(bh + (size_t)n * Hc),
                    (const float*)(bh + (size_t)n * Hc),
                    (__half*)pA3);
            }
            {
                cudaLaunchConfig_t c = pdl_cfg(dim3(96, 1, 3), dim3(256), DSM);
                cudaLaunchKernelEx(&c, mma_gemm_k,
                    (const __half*)pA3, (const __half*)(base + R3OFF),
                    (float*)pP3, 6144, 21, 1, 0, 0);
            }

            int type, nextType;
            const float *cmF = nullptr, *cmB = nullptr, *nmF = nullptr, *nmB = nullptr;
            int ciF = 0, ciB = 0, niF = 0, niB = 0;
            if (sub == 0) {
                type = 1; nextType = 0; nmF = mF; niF = 0; nmB = mB; niB = 1;
            } else if (sub == 1) {
                type = 0; nextType = 0;
                cmF = mF; ciF = 0; cmB = mB; ciB = 1;
                nmF = mF; niF = 1; nmB = mB; niB = 0;
            } else if (sub == 2) {
                type = 0; nextType = 1; cmF = mF; ciF = 1; cmB = mB; ciB = 0;
            } else {
                type = 1; nextType = 1;
            }
            {
                cudaLaunchConfig_t c = pdl_cfg(dim3(128), dim3(256), 0);
                cudaLaunchKernelEx(&c, ep_k, type, eps,
                    (const float*)(bs + (size_t)n * Dc),
                    (const float*)(cs + (size_t)n * Dc),
                    (const float*)(btr + (size_t)n * Dc),
                    (const float*)(bq + (size_t)n * Dc),
                    (const float*)(cq + (size_t)n * Dc),
                    cmF, ciF, cmB, ciB,
                    nextType, nmF, niF, nmB, niB);
            }
        }
    }

    {
        cudaLaunchConfig_t c = pdl_cfg(dim3(64), dim3(256), 0);
        cudaLaunchKernelEx(&c, final_k, position, momf, momb, u_dir, u_acc, out);
    }
}